// round 16
// baseline (speedup 1.0000x reference)
#include <cuda_runtime.h>
#include <cuda_fp16.h>
#include <cstdint>

// GhostLinearTandem, PDL-pipelined two-pass (no streams/events -> no allocs):
//  Same R14 kernels split into 4 N-quarters, all on the capture stream.
//  Chain dq0,gemm0,dq1,gemm1,...: every launch carries the
//  ProgrammaticStreamSerialization attribute. gemm_k fires
//  griddepcontrol.launch_dependents at entry -> dq_{k+1} runs CONCURRENTLY
//  with gemm_k (dq never reads gemm output, so it skips griddepcontrol.wait).
//  dq kernels never trigger early -> gemm_k still starts only after dq_k
//  completes (gemm_k does griddepcontrol.wait for memory visibility).

#define M_TOTAL 512
#define N_TOTAL 8192
#define K_TOTAL 4096
#define NQ 4
#define NQUARTER (N_TOTAL / NQ)   // 2048 rows per quarter

__device__ __align__(16) __half g_W[(size_t)N_TOTAL * K_TOTAL];   // 64 MiB
__device__ __align__(16) __half g_xh[(size_t)M_TOTAL * K_TOTAL];  // 4 MiB

__device__ __forceinline__ uint32_t smem_u32(const void* p) {
    uint32_t a;
    asm("{ .reg .u64 t; cvta.to.shared.u64 t, %1; cvt.u32.u64 %0, t; }"
        : "=r"(a) : "l"(p));
    return a;
}
#define SWZ128(off) ((off) ^ (((off) >> 3) & 0x70))

#define GDC_WAIT()   asm volatile("griddepcontrol.wait;" ::: "memory")
#define GDC_LAUNCH() asm volatile("griddepcontrol.launch_dependents;")

#define CP16(dst, src) \
    asm volatile("cp.async.cg.shared.global [%0], [%1], 16;" :: "r"(dst), "l"(src))
#define CP_COMMIT() asm volatile("cp.async.commit_group;")
#define CP_WAIT1()  asm volatile("cp.async.wait_group 1;")

#define LDSM_X4(r0, r1, r2, r3, addr)                                     \
    asm volatile("ldmatrix.sync.aligned.m8n8.x4.shared.b16 {%0,%1,%2,%3}, [%4];" \
                 : "=r"(r0), "=r"(r1), "=r"(r2), "=r"(r3) : "r"(addr))

#define MMA_F16(d, a0, a1, a2, a3, b0, b1)                             \
    asm volatile(                                                      \
        "mma.sync.aligned.m16n8k16.row.col.f32.f16.f16.f32 "           \
        "{%0,%1,%2,%3}, {%4,%5,%6,%7}, {%8,%9}, {%0,%1,%2,%3};\n"      \
        : "+f"((d)[0]), "+f"((d)[1]), "+f"((d)[2]), "+f"((d)[3])       \
        : "r"(a0), "r"(a1), "r"(a2), "r"(a3), "r"(b0), "r"(b1))

// ---------------------------------------------------------------- pass 1
__global__ __launch_bounds__(1024)
void ghost_dequant(const int* __restrict__ base_idx,
                   const int* __restrict__ fine_idx,
                   const float* __restrict__ scale,
                   const float* __restrict__ lut,
                   const float* __restrict__ x,
                   int n_base, int do_x) {
    // No griddepcontrol.wait: runs concurrently with the preceding gemm
    // quarter (no data dependency on it). Dependents released at completion.
    extern __shared__ __half lut_s[];  // 65536 fp16 = 128KB
    #pragma unroll 4
    for (int i = threadIdx.x; i < 65536; i += 1024)
        lut_s[i] = __float2half_rn(lut[i]);
    __syncthreads();

    size_t t = (size_t)blockIdx.x * blockDim.x + threadIdx.x;
    size_t stride = (size_t)gridDim.x * blockDim.x;

    if (do_x) {
        const float4* xp = (const float4*)x;
        for (size_t g = t; g < (size_t)M_TOTAL * K_TOTAL / 8; g += stride) {
            float4 u = xp[2 * g], v = xp[2 * g + 1];
            __half2 h[4] = {__floats2half2_rn(u.x, u.y), __floats2half2_rn(u.z, u.w),
                            __floats2half2_rn(v.x, v.y), __floats2half2_rn(v.z, v.w)};
            *(uint4*)&g_xh[g * 8] = *(uint4*)h;
        }
    }

    const int4* bp = (const int4*)base_idx;
    const int4* fp = (const int4*)fine_idx;
    const size_t gq0 = (size_t)n_base * (K_TOTAL / 8);
    const size_t NGQ = (size_t)NQUARTER * (K_TOTAL / 8);
    #pragma unroll 2
    for (size_t gl = t; gl < NGQ; gl += stride) {
        size_t g = gq0 + gl;
        int row = (int)(g >> 9);
        float scl = __ldg(&scale[row]);
        int4 b0 = bp[2 * g], b1 = bp[2 * g + 1];
        int4 f0 = fp[2 * g], f1 = fp[2 * g + 1];
        __half2 h[4];
        h[0] = __floats2half2_rn(__half2float(lut_s[(b0.x << 8) + f0.x]) * scl,
                                 __half2float(lut_s[(b0.y << 8) + f0.y]) * scl);
        h[1] = __floats2half2_rn(__half2float(lut_s[(b0.z << 8) + f0.z]) * scl,
                                 __half2float(lut_s[(b0.w << 8) + f0.w]) * scl);
        h[2] = __floats2half2_rn(__half2float(lut_s[(b1.x << 8) + f1.x]) * scl,
                                 __half2float(lut_s[(b1.y << 8) + f1.y]) * scl);
        h[3] = __floats2half2_rn(__half2float(lut_s[(b1.z << 8) + f1.z]) * scl,
                                 __half2float(lut_s[(b1.w << 8) + f1.w]) * scl);
        *(uint4*)&g_W[g * 8] = *(uint4*)h;
    }
}

// ---------------------------------------------------------------- pass 2 (R14)
#define BM 128
#define BN 128
#define BKH 64
#define NS (K_TOTAL / BKH)          // 64 stages
#define NSLOT 3
#define A_BYTES (BM * 128)
#define STAGE_BYTES (2 * A_BYTES)
#define SMEM_GEMM (NSLOT * STAGE_BYTES)  // 98304
#define THREADS 128

__global__ __launch_bounds__(THREADS, 2)
void ghost_gemm(float* __restrict__ out, int n_base) {
    // Wait for our dq quarter's writes to be visible, then immediately
    // release the next dq quarter to run concurrently with us.
    GDC_WAIT();
    GDC_LAUNCH();

    extern __shared__ char smem[];
    const uint32_t sb = smem_u32(smem);
    const int tid = threadIdx.x;
    const int warp = tid >> 5, lane = tid & 31;
    const int m0 = blockIdx.x * BM;   // M fastest -> W L2 reuse
    const int n0 = n_base + blockIdx.y * BN;

    const __half* Ag = g_xh + (size_t)m0 * K_TOTAL;
    const __half* Bg = g_W + (size_t)n0 * K_TOTAL;

    auto load_stage = [&](int s, int slot) {
        const int kh = s * BKH;
        #pragma unroll
        for (int i = 0; i < 16; i++) {
            int c = tid + i * THREADS;
            int cc = c & 1023;
            int row = cc >> 3, ci = cc & 7;
            uint32_t dst = sb + slot * STAGE_BYTES + ((c < 1024) ? 0 : A_BYTES) +
                           SWZ128(row * 128 + ci * 16);
            const __half* src = (c < 1024)
                ? Ag + (size_t)row * K_TOTAL + kh + ci * 8
                : Bg + (size_t)row * K_TOTAL + kh + ci * 8;
            CP16(dst, src);
        }
        CP_COMMIT();
    };

    const int warp_m = warp & 1;
    const int warp_n = warp >> 1;

    const int a_row0 = warp_m * 64 + ((lane >> 3) & 1) * 8 + (lane & 7);
    const int a_koff = (lane >> 4) * 8;
    const int b_row0 = warp_n * 64 + ((lane >> 4) & 1) * 8 + (lane & 7);
    const int b_koff = ((lane >> 3) & 1) * 8;

    float acc[4][8][4];
    #pragma unroll
    for (int mt = 0; mt < 4; mt++)
        #pragma unroll
        for (int nt = 0; nt < 8; nt++)
            #pragma unroll
            for (int r = 0; r < 4; r++) acc[mt][nt][r] = 0.0f;

    load_stage(0, 0);
    load_stage(1, 1);

    int slot = 0;
    for (int s = 0; s < NS; ++s) {
        CP_WAIT1();
        __syncthreads();

        if (s + 2 < NS)
            load_stage(s + 2, (slot + 2) % NSLOT);   // ~2 stages of flight
        else
            CP_COMMIT();

        const uint32_t Abase = sb + slot * STAGE_BYTES;
        const uint32_t Bbase = Abase + A_BYTES;

        #pragma unroll
        for (int ks = 0; ks < 4; ks++) {
            const int k0 = ks * 16;
            uint32_t af[4][4], bf[4][4];
            #pragma unroll
            for (int mt = 0; mt < 4; mt++) {
                uint32_t ad = Abase +
                    SWZ128((a_row0 + mt * 16) * 128 + (k0 + a_koff) * 2);
                LDSM_X4(af[mt][0], af[mt][1], af[mt][2], af[mt][3], ad);
            }
            #pragma unroll
            for (int np = 0; np < 4; np++) {
                uint32_t bd = Bbase +
                    SWZ128((b_row0 + np * 16) * 128 + (k0 + b_koff) * 2);
                LDSM_X4(bf[np][0], bf[np][1], bf[np][2], bf[np][3], bd);
            }
            #pragma unroll
            for (int mt = 0; mt < 4; mt++)
                #pragma unroll
                for (int nt = 0; nt < 8; nt++)
                    MMA_F16(acc[mt][nt],
                            af[mt][0], af[mt][1], af[mt][2], af[mt][3],
                            bf[nt >> 1][(nt & 1) * 2],
                            bf[nt >> 1][(nt & 1) * 2 + 1]);
        }

        slot = (slot + 1) % NSLOT;
    }

    const int qid = lane >> 2, tg = lane & 3;
    #pragma unroll
    for (int mt = 0; mt < 4; mt++) {
        #pragma unroll
        for (int nt = 0; nt < 8; nt++) {
            int row = m0 + warp_m * 64 + mt * 16 + qid;
            int col = n0 + warp_n * 64 + nt * 8 + tg * 2;
            *(float2*)&out[(size_t)row * N_TOTAL + col] =
                make_float2(acc[mt][nt][0], acc[mt][nt][1]);
            *(float2*)&out[(size_t)(row + 8) * N_TOTAL + col] =
                make_float2(acc[mt][nt][2], acc[mt][nt][3]);
        }
    }
}

extern "C" void kernel_launch(void* const* d_in, const int* in_sizes, int n_in,
                              void* d_out, int out_size) {
    const float* x        = (const float*)d_in[0];
    const int*   base_idx = (const int*)d_in[1];
    const int*   fine_idx = (const int*)d_in[2];
    const float* scale    = (const float*)d_in[3];
    const float* lut      = (const float*)d_in[4];
    float* out = (float*)d_out;

    cudaFuncSetAttribute(ghost_dequant, cudaFuncAttributeMaxDynamicSharedMemorySize,
                         131072);
    cudaFuncSetAttribute(ghost_gemm, cudaFuncAttributeMaxDynamicSharedMemorySize,
                         SMEM_GEMM);

    cudaLaunchAttribute pdl;
    pdl.id = cudaLaunchAttributeProgrammaticStreamSerialization;
    pdl.val.programmaticStreamSerializationAllowed = 1;

    for (int q = 0; q < NQ; q++) {
        // dequant quarter q (q0 also converts x; full grid. q1-3 sized to fit
        // alongside running gemm quarters).
        {
            cudaLaunchConfig_t cfg = {};
            cfg.gridDim = dim3(q == 0 ? 148 : 64, 1, 1);
            cfg.blockDim = dim3(1024, 1, 1);
            cfg.dynamicSmemBytes = 131072;
            cfg.stream = 0;
            cfg.attrs = &pdl;
            cfg.numAttrs = (q == 0) ? 0 : 1;   // dq_q may start during gemm_{q-1}
            int nb = q * NQUARTER, dox = (q == 0) ? 1 : 0;
            cudaLaunchKernelEx(&cfg, ghost_dequant,
                               base_idx, fine_idx, scale, lut, x, nb, dox);
        }
        // gemm quarter q (waits on dq_q via griddepcontrol.wait; releases
        // dq_{q+1} immediately via launch_dependents).
        {
            cudaLaunchConfig_t cfg = {};
            cfg.gridDim = dim3(M_TOTAL / BM, NQUARTER / BN, 1);  // (4,16)=64
            cfg.blockDim = dim3(THREADS, 1, 1);
            cfg.dynamicSmemBytes = SMEM_GEMM;
            cfg.stream = 0;
            cfg.attrs = &pdl;
            cfg.numAttrs = 1;
            int nb = q * NQUARTER;
            cudaLaunchKernelEx(&cfg, ghost_gemm, out, nb);
        }
    }
}

// round 17
// speedup vs baseline: 1.5082x; 1.5082x over previous
#include <cuda_runtime.h>
#include <cuda_fp16.h>
#include <cstdint>

// GhostLinearTandem, two-pass (R14 banked config + vectorized LUT prologue):
//  pass 1 (ghost_dequant): 1024 thr/CTA, LUT fp16 in smem (float4-vectorized
//    load, 16 iters instead of 64 scalar), x -> fp16, 2x-unrolled idx loop.
//  pass 2 (ghost_gemm): fp16 mma.sync m16n8k16, BM=BN=128, BK=64,
//    4 warps x (64x64), ldmatrix.x4 on SW128 smem, cp.async 3-stage ring with
//    early issue after the barrier (~2 stages of flight), 2 CTAs/SM,
//    grid (4,64) M-fastest (W L2 reuse).

#define M_TOTAL 512
#define N_TOTAL 8192
#define K_TOTAL 4096

__device__ __align__(16) __half g_W[(size_t)N_TOTAL * K_TOTAL];   // 64 MiB
__device__ __align__(16) __half g_xh[(size_t)M_TOTAL * K_TOTAL];  // 4 MiB

__device__ __forceinline__ uint32_t smem_u32(const void* p) {
    uint32_t a;
    asm("{ .reg .u64 t; cvta.to.shared.u64 t, %1; cvt.u32.u64 %0, t; }"
        : "=r"(a) : "l"(p));
    return a;
}
#define SWZ128(off) ((off) ^ (((off) >> 3) & 0x70))

#define CP16(dst, src) \
    asm volatile("cp.async.cg.shared.global [%0], [%1], 16;" :: "r"(dst), "l"(src))
#define CP_COMMIT() asm volatile("cp.async.commit_group;")
#define CP_WAIT1()  asm volatile("cp.async.wait_group 1;")

#define LDSM_X4(r0, r1, r2, r3, addr)                                     \
    asm volatile("ldmatrix.sync.aligned.m8n8.x4.shared.b16 {%0,%1,%2,%3}, [%4];" \
                 : "=r"(r0), "=r"(r1), "=r"(r2), "=r"(r3) : "r"(addr))

#define MMA_F16(d, a0, a1, a2, a3, b0, b1)                             \
    asm volatile(                                                      \
        "mma.sync.aligned.m16n8k16.row.col.f32.f16.f16.f32 "           \
        "{%0,%1,%2,%3}, {%4,%5,%6,%7}, {%8,%9}, {%0,%1,%2,%3};\n"      \
        : "+f"((d)[0]), "+f"((d)[1]), "+f"((d)[2]), "+f"((d)[3])       \
        : "r"(a0), "r"(a1), "r"(a2), "r"(a3), "r"(b0), "r"(b1))

// ---------------------------------------------------------------- pass 1
__global__ __launch_bounds__(1024)
void ghost_dequant(const int* __restrict__ base_idx,
                   const int* __restrict__ fine_idx,
                   const float* __restrict__ scale,
                   const float* __restrict__ lut,
                   const float* __restrict__ x) {
    extern __shared__ __half lut_s[];  // 65536 fp16 = 128KB
    {
        // vectorized LUT load: 16384 float4 -> 16 iterations per thread
        const float4* lp = (const float4*)lut;
        #pragma unroll
        for (int i = threadIdx.x; i < 16384; i += 1024) {
            float4 u = lp[i];
            __half2 h2[2] = {__floats2half2_rn(u.x, u.y),
                             __floats2half2_rn(u.z, u.w)};
            *(uint2*)&lut_s[i * 4] = *(uint2*)h2;
        }
    }
    __syncthreads();

    size_t t = (size_t)blockIdx.x * blockDim.x + threadIdx.x;
    size_t stride = (size_t)gridDim.x * blockDim.x;

    // x fp32 -> fp16
    const float4* xp = (const float4*)x;
    for (size_t g = t; g < (size_t)M_TOTAL * K_TOTAL / 8; g += stride) {
        float4 u = xp[2 * g], v = xp[2 * g + 1];
        __half2 h[4] = {__floats2half2_rn(u.x, u.y), __floats2half2_rn(u.z, u.w),
                        __floats2half2_rn(v.x, v.y), __floats2half2_rn(v.z, v.w)};
        *(uint4*)&g_xh[g * 8] = *(uint4*)h;
    }

    const int4* bp = (const int4*)base_idx;
    const int4* fp = (const int4*)fine_idx;
    const size_t NG = (size_t)N_TOTAL * K_TOTAL / 8;
    #pragma unroll 2
    for (size_t g = t; g < NG; g += stride) {
        int row = (int)(g >> 9);
        float scl = __ldg(&scale[row]);
        int4 b0 = bp[2 * g], b1 = bp[2 * g + 1];
        int4 f0 = fp[2 * g], f1 = fp[2 * g + 1];
        __half2 h[4];
        h[0] = __floats2half2_rn(__half2float(lut_s[(b0.x << 8) + f0.x]) * scl,
                                 __half2float(lut_s[(b0.y << 8) + f0.y]) * scl);
        h[1] = __floats2half2_rn(__half2float(lut_s[(b0.z << 8) + f0.z]) * scl,
                                 __half2float(lut_s[(b0.w << 8) + f0.w]) * scl);
        h[2] = __floats2half2_rn(__half2float(lut_s[(b1.x << 8) + f1.x]) * scl,
                                 __half2float(lut_s[(b1.y << 8) + f1.y]) * scl);
        h[3] = __floats2half2_rn(__half2float(lut_s[(b1.z << 8) + f1.z]) * scl,
                                 __half2float(lut_s[(b1.w << 8) + f1.w]) * scl);
        *(uint4*)&g_W[g * 8] = *(uint4*)h;
    }
}

// ---------------------------------------------------------------- pass 2 (R14)
#define BM 128
#define BN 128
#define BKH 64                      // halves per stage (128 B per row)
#define NS (K_TOTAL / BKH)          // 64 stages
#define NSLOT 3
#define A_BYTES (BM * 128)          // 16384
#define STAGE_BYTES (2 * A_BYTES)   // A + B = 32768
#define SMEM_GEMM (NSLOT * STAGE_BYTES)  // 98304
#define THREADS 128                 // 4 warps, each 64x64

__global__ __launch_bounds__(THREADS, 2)
void ghost_gemm(float* __restrict__ out) {
    extern __shared__ char smem[];
    const uint32_t sb = smem_u32(smem);
    const int tid = threadIdx.x;
    const int warp = tid >> 5, lane = tid & 31;
    const int m0 = blockIdx.x * BM;   // M fastest -> W L2 reuse
    const int n0 = blockIdx.y * BN;

    const __half* Ag = g_xh + (size_t)m0 * K_TOTAL;
    const __half* Bg = g_W + (size_t)n0 * K_TOTAL;

    auto load_stage = [&](int s, int slot) {
        const int kh = s * BKH;
        #pragma unroll
        for (int i = 0; i < 16; i++) {
            int c = tid + i * THREADS;           // 0..2047
            int cc = c & 1023;
            int row = cc >> 3, ci = cc & 7;
            uint32_t dst = sb + slot * STAGE_BYTES + ((c < 1024) ? 0 : A_BYTES) +
                           SWZ128(row * 128 + ci * 16);
            const __half* src = (c < 1024)
                ? Ag + (size_t)row * K_TOTAL + kh + ci * 8
                : Bg + (size_t)row * K_TOTAL + kh + ci * 8;
            CP16(dst, src);
        }
        CP_COMMIT();
    };

    const int warp_m = warp & 1;
    const int warp_n = warp >> 1;

    const int a_row0 = warp_m * 64 + ((lane >> 3) & 1) * 8 + (lane & 7);
    const int a_koff = (lane >> 4) * 8;
    const int b_row0 = warp_n * 64 + ((lane >> 4) & 1) * 8 + (lane & 7);
    const int b_koff = ((lane >> 3) & 1) * 8;

    float acc[4][8][4];
    #pragma unroll
    for (int mt = 0; mt < 4; mt++)
        #pragma unroll
        for (int nt = 0; nt < 8; nt++)
            #pragma unroll
            for (int r = 0; r < 4; r++) acc[mt][nt][r] = 0.0f;

    load_stage(0, 0);
    load_stage(1, 1);

    int slot = 0;
    for (int s = 0; s < NS; ++s) {
        CP_WAIT1();
        __syncthreads();   // stage s resident; MMA(s-1) done in all warps

        if (s + 2 < NS)
            load_stage(s + 2, (slot + 2) % NSLOT);   // ~2 stages of flight
        else
            CP_COMMIT();   // keep wait_group accounting exact

        const uint32_t Abase = sb + slot * STAGE_BYTES;
        const uint32_t Bbase = Abase + A_BYTES;

        #pragma unroll
        for (int ks = 0; ks < 4; ks++) {
            const int k0 = ks * 16;  // halves
            uint32_t af[4][4], bf[4][4];
            #pragma unroll
            for (int mt = 0; mt < 4; mt++) {
                uint32_t ad = Abase +
                    SWZ128((a_row0 + mt * 16) * 128 + (k0 + a_koff) * 2);
                LDSM_X4(af[mt][0], af[mt][1], af[mt][2], af[mt][3], ad);
            }
            #pragma unroll
            for (int np = 0; np < 4; np++) {
                uint32_t bd = Bbase +
                    SWZ128((b_row0 + np * 16) * 128 + (k0 + b_koff) * 2);
                LDSM_X4(bf[np][0], bf[np][1], bf[np][2], bf[np][3], bd);
            }
            #pragma unroll
            for (int mt = 0; mt < 4; mt++)
                #pragma unroll
                for (int nt = 0; nt < 8; nt++)
                    MMA_F16(acc[mt][nt],
                            af[mt][0], af[mt][1], af[mt][2], af[mt][3],
                            bf[nt >> 1][(nt & 1) * 2],
                            bf[nt >> 1][(nt & 1) * 2 + 1]);
        }

        slot = (slot + 1) % NSLOT;
    }

    // epilogue
    const int qid = lane >> 2, tg = lane & 3;
    #pragma unroll
    for (int mt = 0; mt < 4; mt++) {
        #pragma unroll
        for (int nt = 0; nt < 8; nt++) {
            int row = m0 + warp_m * 64 + mt * 16 + qid;
            int col = n0 + warp_n * 64 + nt * 8 + tg * 2;
            *(float2*)&out[(size_t)row * N_TOTAL + col] =
                make_float2(acc[mt][nt][0], acc[mt][nt][1]);
            *(float2*)&out[(size_t)(row + 8) * N_TOTAL + col] =
                make_float2(acc[mt][nt][2], acc[mt][nt][3]);
        }
    }
}

extern "C" void kernel_launch(void* const* d_in, const int* in_sizes, int n_in,
                              void* d_out, int out_size) {
    const float* x        = (const float*)d_in[0];
    const int*   base_idx = (const int*)d_in[1];
    const int*   fine_idx = (const int*)d_in[2];
    const float* scale    = (const float*)d_in[3];
    const float* lut      = (const float*)d_in[4];
    float* out = (float*)d_out;

    cudaFuncSetAttribute(ghost_dequant, cudaFuncAttributeMaxDynamicSharedMemorySize,
                         131072);
    cudaFuncSetAttribute(ghost_gemm, cudaFuncAttributeMaxDynamicSharedMemorySize,
                         SMEM_GEMM);

    ghost_dequant<<<148, 1024, 131072>>>(base_idx, fine_idx, scale, lut, x);
    dim3 grid(M_TOTAL / BM, N_TOTAL / BN);  // (4, 64), M fastest
    ghost_gemm<<<grid, THREADS, SMEM_GEMM>>>(out);
}